// round 7
// baseline (speedup 1.0000x reference)
#include <cuda_runtime.h>
#include <cstddef>

#define F 32
#define P 16

// Flag written by the dtype-detection prepass: 1 if idx/widx are int64, 0 if int32.
__device__ unsigned g_is64;

// jax silently downgrades int64->int32 when x64 is disabled, so the stored dtype
// of idx/widx is environment-dependent. Indices are < 2*M = 400000 < 2^31, so if
// the buffer is int64 every odd 32-bit word (the high half) is exactly 0.
// P(false positive | int32 data) ~ (2.5e-6)^64 ~ 0. Deterministic per input.
__global__ void detect_dtype_kernel(const unsigned* __restrict__ raw) {
    if (threadIdx.x == 0 && blockIdx.x == 0) {
        unsigned acc = 0u;
        #pragma unroll
        for (int i = 0; i < 64; ++i) acc |= raw[2 * i + 1];
        g_is64 = (acc == 0u) ? 1u : 0u;
    }
}

// 2 neurons per warp, 16 lanes per neuron, float2 (2 feature columns) per lane.
// Each gather LDG.64 covers 2 pool rows (2 x 128B lines) -> only ONE within-LDG
// replay wavefront, vs 3 for the float4/LDG.128 layout. idx/w are preloaded one
// element per lane (coalesced) and broadcast with width-16 partition shuffles
// whose source lane is a compile-time immediate.
__global__ __launch_bounds__(256)
void linear_gather_kernel(const float* __restrict__ values0,
                          const float* __restrict__ values1,
                          const float* __restrict__ w_table,
                          const void*  __restrict__ idx_raw,
                          const void*  __restrict__ widx_raw,
                          float* __restrict__ out,
                          int N, int M) {
    const unsigned is64 = g_is64;
    const int warp = (blockIdx.x * blockDim.x + threadIdx.x) >> 5;
    const int lane = threadIdx.x & 31;
    const int sub  = lane & 15;           // lane within the neuron's 16-lane group
    const int nb   = warp * 2;
    int n = nb + (lane >> 4);             // this group's neuron
    if (nb >= N) return;
    const bool valid = (n < N);
    if (!valid) n = N - 1;                // clamp for loads; store is predicated

    // ---- preload: 1 index + 1 weight per lane (16 per 16-lane group) ----
    int my_i;                             // idx[n*16 + sub]
    long long wrow;
    if (is64) {
        my_i = (int)(((const long long*)idx_raw)[(size_t)n * P + sub]);
        wrow = ((const long long*)widx_raw)[n];
    } else {
        my_i = ((const int*)idx_raw)[(size_t)n * P + sub];
        wrow = ((const int*)widx_raw)[n];
    }
    const float my_w = __ldg(w_table + (size_t)wrow * P + sub);

    // Per-lane feature base pointers (sub*2 cols), values1 pre-shifted by -M rows
    const float* __restrict__ base0 = values0 + sub * 2;
    const float* __restrict__ base1 = values1 + sub * 2 - (size_t)M * F;

    float2 acc = make_float2(0.f, 0.f);

    #pragma unroll
    for (int p = 0; p < P; ++p) {
        // broadcast within the 16-lane partition; source lane p is an immediate
        const int   ip = __shfl_sync(0xffffffffu, my_i, p, 16);
        const float wp = __shfl_sync(0xffffffffu, my_w, p, 16);
        const float* src = (ip < M) ? base0 : base1;
        const float2 v = __ldg((const float2*)(src + (size_t)ip * F));
        acc.x = fmaf(wp, v.x, acc.x);
        acc.y = fmaf(wp, v.y, acc.y);
    }

    if (valid)
        ((float2*)out)[(size_t)n * (F / 2) + sub] = acc;
}

extern "C" void kernel_launch(void* const* d_in, const int* in_sizes, int n_in,
                              void* d_out, int out_size) {
    // metadata order: values0 [M,F] f32, values1 [M,F] f32, w_table [K,P] f32,
    //                 idx [N,P] int64/int32, widx [N] int64/int32
    const float* values0 = (const float*)d_in[0];
    const float* values1 = (const float*)d_in[1];
    const float* w_table = (const float*)d_in[2];
    const void*  idx     = d_in[3];
    const void*  widx    = d_in[4];
    float* out = (float*)d_out;

    const int M = in_sizes[0] / F;   // rows per source layer
    const int N = in_sizes[4];       // output neurons (widx element count)

    detect_dtype_kernel<<<1, 32>>>((const unsigned*)idx);

    const int threads = 256;                       // 8 warps = 16 neurons/block
    const int neurons_per_block = (threads / 32) * 2;
    const int blocks = (N + neurons_per_block - 1) / neurons_per_block;
    linear_gather_kernel<<<blocks, threads>>>(values0, values1, w_table,
                                              idx, widx, out, N, M);
}

// round 8
// speedup vs baseline: 1.1732x; 1.1732x over previous
#include <cuda_runtime.h>
#include <cstddef>

#define F 32
#define P 16
#define NPB 32           // neurons per block (8 warps x 4)
#define SPITCH 17        // smem pairs per neuron, padded: 136B stride -> groups hit distinct banks

// Flag written by the dtype-detection prepass: 1 if idx/widx are int64, 0 if int32.
__device__ unsigned g_is64;

// jax silently downgrades int64->int32 when x64 is disabled, so the stored dtype
// of idx/widx is environment-dependent. Indices are < 2*M = 400000 < 2^31, so if
// the buffer is int64 every odd 32-bit word (the high half) is exactly 0.
// P(false positive | int32 data) ~ (2.5e-6)^64 ~ 0. Deterministic per input.
__global__ void detect_dtype_kernel(const unsigned* __restrict__ raw) {
    if (threadIdx.x == 0 && blockIdx.x == 0) {
        unsigned acc = 0u;
        #pragma unroll
        for (int i = 0; i < 64; ++i) acc |= raw[2 * i + 1];
        g_is64 = (acc == 0u) ? 1u : 0u;
    }
}

// 4 neurons per warp, 8 lanes per neuron, float4 per lane (R4 layout), but the
// per-step (idx, w) broadcast is ONE LDS.64 from a block-staged smem table
// instead of TWO SHFLs — shuffles ride the same L1/shared crossbar as loads,
// and were 2/3 of the mainloop MIO instruction count.
__global__ __launch_bounds__(256)
void linear_gather_kernel(const float* __restrict__ values0,
                          const float* __restrict__ values1,
                          const float* __restrict__ w_table,
                          const void*  __restrict__ idx_raw,
                          const void*  __restrict__ widx_raw,
                          float* __restrict__ out,
                          int N, int M) {
    __shared__ int2 s_pair[NPB * SPITCH];

    const unsigned is64 = g_is64;
    const int nb = blockIdx.x * NPB;

    // ---- stage: pack (idx:int32, w:f32) pairs for this block's 32 neurons ----
    // j = ln*16 + p; consecutive threads -> consecutive p: idx reads coalesced,
    // w_table reads are 64B broadcast segments (L1/L2-hot).
    #pragma unroll
    for (int j = threadIdx.x; j < NPB * P; j += 256) {
        const int ln = j >> 4;
        const int p  = j & 15;
        int n = nb + ln;
        if (n >= N) n = N - 1;                    // clamp (stores predicated later)
        int ipv;
        long long wrow;
        if (is64) {
            ipv  = (int)(((const long long*)idx_raw)[(size_t)n * P + p]);
            wrow = ((const long long*)widx_raw)[n];
        } else {
            ipv  = ((const int*)idx_raw)[(size_t)n * P + p];
            wrow = ((const int*)widx_raw)[n];
        }
        const float w = __ldg(w_table + (size_t)wrow * P + p);
        s_pair[ln * SPITCH + p] = make_int2(ipv, __float_as_int(w));
    }
    __syncthreads();

    // ---- mainloop: 4 neurons per warp, 8 lanes x float4 per neuron ----
    const int lane = threadIdx.x & 31;
    const int wl   = threadIdx.x >> 5;        // warp in block
    const int grp  = lane >> 3;               // neuron group within warp
    const int sub  = lane & 7;                // lane within group (4 feature cols)
    const int lnrn = wl * 4 + grp;            // local neuron
    int n = nb + lnrn;
    const bool valid = (n < N);
    if (!valid) n = N - 1;

    const float* __restrict__ base0 = values0 + sub * 4;
    const float* __restrict__ base1 = values1 + sub * 4 - (size_t)M * F;
    const int sb = lnrn * SPITCH;

    float4 acc = make_float4(0.f, 0.f, 0.f, 0.f);

    #pragma unroll
    for (int p = 0; p < P; ++p) {
        const int2  pr = s_pair[sb + p];      // 8-lane broadcast, conflict-free
        const float wp = __int_as_float(pr.y);
        const float* src = (pr.x < M) ? base0 : base1;
        const float4 v = __ldg((const float4*)(src + (size_t)pr.x * F));
        acc.x = fmaf(wp, v.x, acc.x);
        acc.y = fmaf(wp, v.y, acc.y);
        acc.z = fmaf(wp, v.z, acc.z);
        acc.w = fmaf(wp, v.w, acc.w);
    }

    if (valid)
        ((float4*)out)[(size_t)n * (F / 4) + sub] = acc;
}

extern "C" void kernel_launch(void* const* d_in, const int* in_sizes, int n_in,
                              void* d_out, int out_size) {
    // metadata order: values0 [M,F] f32, values1 [M,F] f32, w_table [K,P] f32,
    //                 idx [N,P] int64/int32, widx [N] int64/int32
    const float* values0 = (const float*)d_in[0];
    const float* values1 = (const float*)d_in[1];
    const float* w_table = (const float*)d_in[2];
    const void*  idx     = d_in[3];
    const void*  widx    = d_in[4];
    float* out = (float*)d_out;

    const int M = in_sizes[0] / F;   // rows per source layer
    const int N = in_sizes[4];       // output neurons (widx element count)

    detect_dtype_kernel<<<1, 32>>>((const unsigned*)idx);

    const int blocks = (N + NPB - 1) / NPB;
    linear_gather_kernel<<<blocks, 256>>>(values0, values1, w_table,
                                          idx, widx, out, N, M);
}

// round 9
// speedup vs baseline: 1.2751x; 1.0869x over previous
#include <cuda_runtime.h>
#include <cstddef>

#define F 32
#define P 16

// Flag written by the dtype-detection prepass: 1 if idx/widx are int64, 0 if int32.
__device__ unsigned g_is64;

// jax silently downgrades int64->int32 when x64 is disabled, so the stored dtype
// of idx/widx is environment-dependent. Indices are < 2*M = 400000 < 2^31, so if
// the buffer is int64 every odd 32-bit word (the high half) is exactly 0.
// P(false positive | int32 data) ~ (2.5e-6)^64 ~ 0. Deterministic per input.
__global__ void detect_dtype_kernel(const unsigned* __restrict__ raw) {
    if (threadIdx.x == 0 && blockIdx.x == 0) {
        unsigned acc = 0u;
        #pragma unroll
        for (int i = 0; i < 64; ++i) acc |= raw[2 * i + 1];
        g_is64 = (acc == 0u) ? 1u : 0u;
    }
}

// 4 neurons per warp, 8 lanes per neuron, float4 (4 feature columns) per lane
// (the proven-fastest R4 layout). Pool gathers use ld.global.cg (__ldcg):
// the pool is L2-resident but has ~0% L1 hit rate, so L1 line allocation on
// 8M gather misses is pure L1tex overhead — bypass it. idx/w_table keep the
// L1-cached path (genuinely hot).
__global__ __launch_bounds__(256)
void linear_gather_kernel(const float* __restrict__ values0,
                          const float* __restrict__ values1,
                          const float* __restrict__ w_table,
                          const void*  __restrict__ idx_raw,
                          const void*  __restrict__ widx_raw,
                          float* __restrict__ out,
                          int N, int M) {
    const unsigned is64 = g_is64;
    const int warp = (blockIdx.x * blockDim.x + threadIdx.x) >> 5;
    const int lane = threadIdx.x & 31;
    const int sub  = lane & 7;        // lane within the neuron's 8-lane group
    const int nb   = warp * 4;
    int n = nb + (lane >> 3);         // this group's neuron
    if (nb >= N) return;
    const bool valid = (n < N);
    if (!valid) n = N - 1;            // clamp for loads; store is predicated

    // ---- preload: 2 indices + 2 weights per lane (16 per 8-lane group) ----
    int ia, ib;                       // idx[n*16 + 2*sub], idx[n*16 + 2*sub+1]
    long long wrow;
    if (is64) {
        const longlong2 L =
            ((const longlong2*)idx_raw)[(size_t)n * (P / 2) + sub];
        ia = (int)L.x; ib = (int)L.y;
        wrow = ((const long long*)widx_raw)[n];
    } else {
        const int2 L = ((const int2*)idx_raw)[(size_t)n * (P / 2) + sub];
        ia = L.x; ib = L.y;
        wrow = ((const int*)widx_raw)[n];
    }
    const float2 w2 =
        ((const float2*)(w_table + (size_t)wrow * P))[sub];  // w[2sub], w[2sub+1]

    // Per-lane feature base pointers (sub*4 columns), values1 pre-shifted by -M rows
    const float* __restrict__ base0 = values0 + sub * 4;
    const float* __restrict__ base1 = values1 + sub * 4 - (size_t)M * F;

    float4 acc = make_float4(0.f, 0.f, 0.f, 0.f);

    #pragma unroll
    for (int p = 0; p < P; ++p) {
        // broadcast within the 8-lane partition; source lane p/2 is an immediate
        const int   ip = (p & 1) ? __shfl_sync(0xffffffffu, ib, p >> 1, 8)
                                 : __shfl_sync(0xffffffffu, ia, p >> 1, 8);
        const float wp = (p & 1) ? __shfl_sync(0xffffffffu, w2.y, p >> 1, 8)
                                 : __shfl_sync(0xffffffffu, w2.x, p >> 1, 8);
        const float* src = (ip < M) ? base0 : base1;
        const float4 v = __ldcg((const float4*)(src + (size_t)ip * F));
        acc.x = fmaf(wp, v.x, acc.x);
        acc.y = fmaf(wp, v.y, acc.y);
        acc.z = fmaf(wp, v.z, acc.z);
        acc.w = fmaf(wp, v.w, acc.w);
    }

    if (valid)
        ((float4*)out)[(size_t)n * (F / 4) + sub] = acc;
}

extern "C" void kernel_launch(void* const* d_in, const int* in_sizes, int n_in,
                              void* d_out, int out_size) {
    // metadata order: values0 [M,F] f32, values1 [M,F] f32, w_table [K,P] f32,
    //                 idx [N,P] int64/int32, widx [N] int64/int32
    const float* values0 = (const float*)d_in[0];
    const float* values1 = (const float*)d_in[1];
    const float* w_table = (const float*)d_in[2];
    const void*  idx     = d_in[3];
    const void*  widx    = d_in[4];
    float* out = (float*)d_out;

    const int M = in_sizes[0] / F;   // rows per source layer
    const int N = in_sizes[4];       // output neurons (widx element count)

    detect_dtype_kernel<<<1, 32>>>((const unsigned*)idx);

    const int threads = 256;                       // 8 warps = 32 neurons/block
    const int neurons_per_block = (threads / 32) * 4;
    const int blocks = (N + neurons_per_block - 1) / neurons_per_block;
    linear_gather_kernel<<<blocks, threads>>>(values0, values1, w_table,
                                              idx, widx, out, N, M);
}